// round 16
// baseline (speedup 1.0000x reference)
#include <cuda_runtime.h>

#define IMG 256
#define NEAR_F 0.1f
#define FAR_F 100.0f
#define REPS 1e-8f
#define ORIG 1024.0f

#define BMAX 4
#define VMAX 5000
#define FMAX 10000
#define NFACE (BMAX * FMAX)
#define TPI 16                        // 16x16 tiles of 16x16 px per image
#define TSZ 16
#define NTILEMAX (BMAX * TPI * TPI)   // 1024
#define CAP 8192
#define CH 32
#define SPLITR 8                      // max slices per tile
#define GPF 2                         // lanes per face in prepfill
#define CULL_M 1e-4f
#define WMARG 1e-4f                   // fwd/rev agreement margin

// ---------------- scratch ----------------
__device__ float  g_vndc[BMAX * VMAX * 3];
__device__ float4 g_rec[NFACE * 5];
__device__ float  g_zminf[NFACE];
__device__ int    g_fill[NTILEMAX];
__device__ int    g_listA[NTILEMAX * CAP];
__device__ int    g_listB[NTILEMAX * CAP];

__device__ __forceinline__ int zbucket(float z) {
    int q = (int)floorf((z - 0.5f) * 64.0f);
    return max(0, min(255, q));
}
__device__ __forceinline__ float zbound(int q) {
    return (q <= 0) ? 0.0f : (0.5f + (float)q * 0.015625f - 1e-4f);
}

// ---------------- projection ----------------
__global__ void project_kernel(const float* __restrict__ verts,
                               const float* __restrict__ K,
                               const float* __restrict__ R,
                               const float* __restrict__ t,
                               const float* __restrict__ dist,
                               int B, int V) {
    int idx = blockIdx.x * blockDim.x + threadIdx.x;
    if (idx >= B * V) return;
    int b = idx / V;
    const float* vp = verts + (size_t)idx * 3;
    const float* Rb = R + b * 9;
    const float* tb = t + b * 3;
    const float* Kb = K + b * 9;
    const float* db = dist + b * 5;

    float vx = vp[0], vy = vp[1], vz = vp[2];
    float x = Rb[0] * vx + Rb[1] * vy + Rb[2] * vz + tb[0];
    float y = Rb[3] * vx + Rb[4] * vy + Rb[5] * vz + tb[1];
    float z = Rb[6] * vx + Rb[7] * vy + Rb[8] * vz + tb[2];

    float x_ = x / (z + 1e-9f);
    float y_ = y / (z + 1e-9f);
    float k1 = db[0], k2 = db[1], p1 = db[2], p2 = db[3], k3 = db[4];
    float r2 = x_ * x_ + y_ * y_;
    float rad = 1.0f + k1 * r2 + k2 * r2 * r2 + k3 * r2 * r2 * r2;
    float x__ = x_ * rad + 2.0f * p1 * x_ * y_ + p2 * (r2 + 2.0f * x_ * x_);
    float y__ = y_ * rad + p1 * (r2 + 2.0f * y_ * y_) + 2.0f * p2 * x_ * y_;

    float u  = Kb[0] * x__ + Kb[1] * y__ + Kb[2];
    float vc = Kb[3] * x__ + Kb[4] * y__ + Kb[5];
    vc = ORIG - vc;
    u  = 2.0f * (u  - ORIG * 0.5f) / ORIG;
    vc = 2.0f * (vc - ORIG * 0.5f) / ORIG;

    float* o = g_vndc + (size_t)idx * 3;
    o[0] = u; o[1] = vc; o[2] = z;
}

// ---------------- 2-lanes-per-face prep + fill ----------------
__global__ void prepfill_kernel(const int* __restrict__ faces, int B, int V, int F) {
    int gid  = blockIdx.x * blockDim.x + threadIdx.x;
    int idx  = gid / GPF;              // 2 lanes per face
    int lane = gid % GPF;
    if (idx >= B * F) return;
    int b = idx / F;
    const int* fp = faces + (size_t)idx * 3;
    int i0 = fp[0], i1 = fp[1], i2 = fp[2];       // broadcast within group
    const float* base = g_vndc + (size_t)b * V * 3;
    float x0 = base[i0*3+0], y0 = base[i0*3+1], z0 = base[i0*3+2];
    float x1 = base[i1*3+0], y1 = base[i1*3+1], z1 = base[i1*3+2];
    float x2 = base[i2*3+0], y2 = base[i2*3+1], z2 = base[i2*3+2];

    if (!(z0 > REPS && z1 > REPS && z2 > REPS)) return;

    float df = (y1 - y2) * (x0 - x2) + (x2 - x1) * (y0 - y2);
    float dr = (y1 - y0) * (x2 - x0) + (x0 - x1) * (y2 - y0);
    bool okf = fabsf(df) > REPS;
    bool okr = fabsf(dr) > REPS;
    if (!okf && !okr) return;

    float xmin = fminf(x0, fminf(x1, x2)), xmax = fmaxf(x0, fmaxf(x1, x2));
    float ymin = fminf(y0, fminf(y1, y2)), ymax = fmaxf(y0, fmaxf(y1, y2));
    const float Sf = (float)IMG;
    int c_lo = max(0,       (int)floorf((xmin * Sf + Sf - 1.0f) * 0.5f));
    int c_hi = min(IMG - 1, (int)ceilf ((xmax * Sf + Sf - 1.0f) * 0.5f));
    int r_lo = max(0,       (int)floorf((ymin * Sf + Sf - 1.0f) * 0.5f));
    int r_hi = min(IMG - 1, (int)ceilf ((ymax * Sf + Sf - 1.0f) * 0.5f));
    if (c_lo > c_hi || r_lo > r_hi) return;

    float zmf = fminf(z0, fminf(z1, z2));

    float nanv = __int_as_float(0x7fffffff);
    float invdf = okf ? (1.0f / df) : nanv;
    float invdr = okr ? (1.0f / dr) : nanv;
    float iz0 = 1.0f / z0, iz1 = 1.0f / z1, iz2 = 1.0f / z2;

    float4 r1; r1.x = y1 - y2; r1.y = x2 - x1; r1.z = y2 - y0; r1.w = x0 - x2;

    if (lane == 0) {
        g_zminf[idx] = zmf;
        float4 r0; r0.x = x2;      r0.y = y2;      r0.z = x0;      r0.w = y0;
        float4 r2f; r2f.x = y1 - y0; r2f.y = x0 - x1; r2f.z = y0 - y2; r2f.w = x2 - x0;
        float4 r3; r3.x = invdf;   r3.y = invdr;   r3.z = zmf;       r3.w = iz0 - iz2;
        float4 r4; r4.x = iz1 - iz2; r4.y = iz2;   r4.z = iz1 - iz0; r4.w = iz0;
        g_rec[idx*5+0] = r0; g_rec[idx*5+1] = r1; g_rec[idx*5+2] = r2f;
        g_rec[idx*5+3] = r3; g_rec[idx*5+4] = r4;
    }

    // tile loop distributed across the 2 lanes of this face's group
    float a0 = r1.x * invdf, b0 = r1.y * invdf;
    float a1 = r1.z * invdf, b1 = r1.w * invdf;
    float a2 = -a0 - a1,     b2 = -b0 - b1;
    int tbase = b * TPI * TPI;
    int ty0 = r_lo >> 4, ty1 = r_hi >> 4;
    int tx0 = c_lo >> 4, tx1 = c_hi >> 4;
    int ntx = tx1 - tx0 + 1;
    int ntot = ntx * (ty1 - ty0 + 1);

    for (int i = lane; i < ntot; i += GPF) {
        int ty = ty0 + i / ntx;
        int tx = tx0 + i - (i / ntx) * ntx;
        float ylo = (2.0f * (float)(ty * TSZ)           + 1.0f - Sf) / Sf - y2;
        float yhi = (2.0f * (float)(ty * TSZ + TSZ - 1) + 1.0f - Sf) / Sf - y2;
        float xlo = (2.0f * (float)(tx * TSZ)           + 1.0f - Sf) / Sf - x2;
        float xhi = (2.0f * (float)(tx * TSZ + TSZ - 1) + 1.0f - Sf) / Sf - x2;

        float m0 = a0 * (a0 >= 0.f ? xhi : xlo) + b0 * (b0 >= 0.f ? yhi : ylo);
        float m1 = a1 * (a1 >= 0.f ? xhi : xlo) + b1 * (b1 >= 0.f ? yhi : ylo);
        float m2 = 1.0f + a2 * (a2 >= 0.f ? xhi : xlo) + b2 * (b2 >= 0.f ? yhi : ylo);
        if (m0 < -CULL_M || m1 < -CULL_M || m2 < -CULL_M) continue;

        int t = tbase + ty * TPI + tx;
        int pos = atomicAdd(&g_fill[t], 1);
        if (pos < CAP) g_listA[t * CAP + pos] = idx;
    }
}

// ---------------- per-tile counting sort by z-bucket (shfl scan) ----------------
__global__ void sort_kernel() {
    int tile = blockIdx.x;
    int len  = min(g_fill[tile], CAP);
    if (len == 0) return;
    int base = tile * CAP;
    int tid = threadIdx.x;
    int lane = tid & 31, wrp = tid >> 5;
    const unsigned FULL = 0xffffffffu;

    __shared__ int cnt[256];
    __shared__ int off[256];
    __shared__ int wsum[8];
    cnt[tid] = 0;
    __syncthreads();

    for (int i = tid; i < len; i += 256) {
        int f = g_listA[base + i];
        atomicAdd(&cnt[zbucket(g_zminf[f])], 1);
    }
    __syncthreads();

    int v = cnt[tid];
    int x = v;
    #pragma unroll
    for (int o = 1; o < 32; o <<= 1) {
        int y = __shfl_up_sync(FULL, x, o);
        if (lane >= o) x += y;
    }
    if (lane == 31) wsum[wrp] = x;
    __syncthreads();
    if (tid < 8) {
        int s = wsum[tid];
        int xx = s;
        #pragma unroll
        for (int o = 1; o < 8; o <<= 1) {
            int y = __shfl_up_sync(0xffu, xx, o);
            if (tid >= o) xx += y;
        }
        wsum[tid] = xx - s;
    }
    __syncthreads();
    off[tid] = x + wsum[wrp] - v;
    __syncthreads();

    for (int i = tid; i < len; i += 256) {
        int f = g_listA[base + i];
        int q = zbucket(g_zminf[f]);
        int pos = atomicAdd(&off[q], 1);
        g_listB[base + pos] = f;
    }
}

// ---------------- init output ----------------
__global__ void init_kernel(float4* __restrict__ out, int n4) {
    int i = blockIdx.x * blockDim.x + threadIdx.x;
    if (i < n4) { float4 v; v.x = v.y = v.z = v.w = FAR_F; out[i] = v; }
}

// ---------------- raster: adaptive slices + reg-double-buffered staging ----------------
__global__ void __launch_bounds__(256) raster_tiles(float* __restrict__ out) {
    int tile  = blockIdx.x / SPLITR;
    int slice = blockIdx.x % SPLITR;
    int len = min(g_fill[tile], CAP);
    // adaptive number of slices: one per ~512 faces, capped at SPLITR
    int nsl = min(SPLITR, 1 + (len >> 9));
    if (slice >= nsl) return;
    int jstart = slice * CH;
    if (len <= jstart) return;

    int b  = tile >> 8;
    int tt = tile & 255;
    int ty = tt >> 4, tx = tt & 15;
    int tid = threadIdx.x;
    int r = ty * TSZ + (tid >> 4);
    int c = tx * TSZ + (tid & 15);
    const float Sf = (float)IMG;
    float xp = (2.0f * (float)c + 1.0f - Sf) / Sf;
    float yp = (2.0f * (float)r + 1.0f - Sf) / Sf;

    int basei = tile * CAP;
    const unsigned FULL = 0xffffffffu;
    int stride = CH * nsl;

    __shared__ float4 srec[CH * 5];
    float zmin = FAR_F;

    // prologue: prefetch first chunk into registers (<=1 float4/thread)
    float4 pre;
    {
        int n0 = min(CH, len - jstart);
        if (tid < n0 * 5) {
            int m = tid / 5, q = tid - m * 5;
            int fidx = g_listB[basei + jstart + m];
            pre = g_rec[fidx * 5 + q];
        }
    }

    for (int j = jstart; j < len; j += stride) {
        int n = min(CH, len - j);
        __syncthreads();
        if (tid < n * 5) srec[tid] = pre;
        __syncthreads();

        // prefetch next chunk: gmem latency overlaps the compute below
        int jn = j + stride;
        if (jn < len) {
            int nn = min(CH, len - jn);
            if (tid < nn * 5) {
                int m = tid / 5, q = tid - m * 5;
                int fidx = g_listB[basei + jn + m];
                pre = g_rec[fidx * 5 + q];
            }
        }

        float bound = zbound(zbucket(srec[3].z));
        if (__syncthreads_and(zmin <= bound)) break;

        for (int m = 0; m < n; m++) {
            float4 q3 = srec[m*5+3];
            if (!__ballot_sync(FULL, q3.z < zmin)) continue;

            float4 q0 = srec[m*5+0];
            float4 q1 = srec[m*5+1];

            float dxf = xp - q0.x, dyf = yp - q0.y;
            float w0 = (q1.x * dxf + q1.y * dyf) * q3.x;
            float w1 = (q1.z * dxf + q1.w * dyf) * q3.x;
            float w2 = 1.0f - w0 - w1;
            bool inf_ = (w0 >= 0.0f) && (w1 >= 0.0f) && (w2 >= 0.0f);
            bool safe = (fabsf(w0) > WMARG) && (fabsf(w1) > WMARG) && (fabsf(w2) > WMARG);

            bool in_ = inf_;
            bool userev = false;
            float w0r = 0.f, w1r = 0.f;
            if (__ballot_sync(FULL, !safe)) {
                float4 q2 = srec[m*5+2];
                float dxr = xp - q0.z, dyr = yp - q0.w;
                w0r = (q2.x * dxr + q2.y * dyr) * q3.y;
                w1r = (q2.z * dxr + q2.w * dyr) * q3.y;
                float w2r = 1.0f - w0r - w1r;
                bool inr_ = (w0r >= 0.0f) && (w1r >= 0.0f) && (w2r >= 0.0f);
                in_ = inf_ || inr_;
                userev = (!inf_) && inr_;
            }

            if (in_) {
                float4 q4 = srec[m*5+4];
                float zinv = userev ? fmaf(w1r, q4.z, fmaf(w0r, -q3.w, q4.w))
                                    : fmaf(w1,  q4.x, fmaf(w0,   q3.w, q4.y));
                float zp = (zinv > REPS) ? __fdividef(1.0f, zinv) : 1.0f;
                if (zp > NEAR_F && zp < FAR_F) zmin = fminf(zmin, zp);
            }
        }
    }

    if (zmin < FAR_F) {
        int* addr = (int*)&out[((size_t)b * IMG + (IMG - 1 - r)) * IMG + c];
        atomicMin(addr, __float_as_int(zmin));
    }
}

extern "C" void kernel_launch(void* const* d_in, const int* in_sizes, int n_in,
                              void* d_out, int out_size) {
    const float* verts = (const float*)d_in[0];
    const int*   faces = (const int*)d_in[1];
    const float* K     = (const float*)d_in[2];
    const float* R     = (const float*)d_in[3];
    const float* t     = (const float*)d_in[4];
    const float* dist  = (const float*)d_in[5];
    float* out = (float*)d_out;

    int B = in_sizes[2] / 9;
    int V = in_sizes[0] / (3 * B);
    int F = in_sizes[1] / (3 * B);
    int ntile = B * TPI * TPI;

    void* fill_ptr = nullptr;
    cudaGetSymbolAddress(&fill_ptr, g_fill);

    int nv = B * V;
    project_kernel<<<(nv + 255) / 256, 256>>>(verts, K, R, t, dist, B, V);

    cudaMemsetAsync(fill_ptr, 0, ntile * sizeof(int));

    int nf = B * F;
    int nthr = nf * GPF;
    prepfill_kernel<<<(nthr + 255) / 256, 256>>>(faces, B, V, F);

    sort_kernel<<<ntile, 256>>>();

    int npix4 = (B * IMG * IMG) / 4;
    init_kernel<<<(npix4 + 255) / 256, 256>>>((float4*)out, npix4);

    raster_tiles<<<ntile * SPLITR, 256>>>(out);
}

// round 17
// speedup vs baseline: 1.1506x; 1.1506x over previous
#include <cuda_runtime.h>

#define IMG 256
#define NEAR_F 0.1f
#define FAR_F 100.0f
#define REPS 1e-8f
#define ORIG 1024.0f

#define BMAX 4
#define VMAX 5000
#define FMAX 10000
#define NFACE (BMAX * FMAX)
#define TPI 16                        // 16x16 tiles of 16x16 px per image
#define TSZ 16
#define NTILEMAX (BMAX * TPI * TPI)   // 1024
#define CAP 8192
#define CH 32
#define SPLITR 8                      // max slices per tile
#define GPF 4                         // lanes per face in prepfill
#define CULL_M 1e-4f
#define WMARG 1e-4f                   // fwd/rev agreement margin

// ---------------- scratch ----------------
__device__ float  g_vndc[BMAX * VMAX * 3];
__device__ float4 g_rec[NFACE * 5];
__device__ float  g_zminf[NFACE];
__device__ int    g_fill[NTILEMAX];
__device__ int    g_listA[NTILEMAX * CAP];   // packed: (bucket<<24) | idx
__device__ int    g_listB[NTILEMAX * CAP];   // plain face idx, bucket-sorted

__device__ __forceinline__ int zbucket(float z) {
    int q = (int)floorf((z - 0.5f) * 64.0f);
    return max(0, min(255, q));
}
__device__ __forceinline__ float zbound(int q) {
    return (q <= 0) ? 0.0f : (0.5f + (float)q * 0.015625f - 1e-4f);
}

// ---------------- projection ----------------
__global__ void project_kernel(const float* __restrict__ verts,
                               const float* __restrict__ K,
                               const float* __restrict__ R,
                               const float* __restrict__ t,
                               const float* __restrict__ dist,
                               int B, int V) {
    int idx = blockIdx.x * blockDim.x + threadIdx.x;
    if (idx >= B * V) return;
    int b = idx / V;
    const float* vp = verts + (size_t)idx * 3;
    const float* Rb = R + b * 9;
    const float* tb = t + b * 3;
    const float* Kb = K + b * 9;
    const float* db = dist + b * 5;

    float vx = vp[0], vy = vp[1], vz = vp[2];
    float x = Rb[0] * vx + Rb[1] * vy + Rb[2] * vz + tb[0];
    float y = Rb[3] * vx + Rb[4] * vy + Rb[5] * vz + tb[1];
    float z = Rb[6] * vx + Rb[7] * vy + Rb[8] * vz + tb[2];

    float x_ = x / (z + 1e-9f);
    float y_ = y / (z + 1e-9f);
    float k1 = db[0], k2 = db[1], p1 = db[2], p2 = db[3], k3 = db[4];
    float r2 = x_ * x_ + y_ * y_;
    float rad = 1.0f + k1 * r2 + k2 * r2 * r2 + k3 * r2 * r2 * r2;
    float x__ = x_ * rad + 2.0f * p1 * x_ * y_ + p2 * (r2 + 2.0f * x_ * x_);
    float y__ = y_ * rad + p1 * (r2 + 2.0f * y_ * y_) + 2.0f * p2 * x_ * y_;

    float u  = Kb[0] * x__ + Kb[1] * y__ + Kb[2];
    float vc = Kb[3] * x__ + Kb[4] * y__ + Kb[5];
    vc = ORIG - vc;
    u  = 2.0f * (u  - ORIG * 0.5f) / ORIG;
    vc = 2.0f * (vc - ORIG * 0.5f) / ORIG;

    float* o = g_vndc + (size_t)idx * 3;
    o[0] = u; o[1] = vc; o[2] = z;
}

// ---------------- 4-lanes-per-face prep + fill ----------------
__global__ void prepfill_kernel(const int* __restrict__ faces, int B, int V, int F) {
    int gid  = blockIdx.x * blockDim.x + threadIdx.x;
    int idx  = gid / GPF;              // 4 lanes per face
    int lane = gid % GPF;
    if (idx >= B * F) return;
    int b = idx / F;
    const int* fp = faces + (size_t)idx * 3;
    int i0 = fp[0], i1 = fp[1], i2 = fp[2];       // broadcast within group
    const float* base = g_vndc + (size_t)b * V * 3;
    float x0 = base[i0*3+0], y0 = base[i0*3+1], z0 = base[i0*3+2];
    float x1 = base[i1*3+0], y1 = base[i1*3+1], z1 = base[i1*3+2];
    float x2 = base[i2*3+0], y2 = base[i2*3+1], z2 = base[i2*3+2];

    if (!(z0 > REPS && z1 > REPS && z2 > REPS)) return;

    float df = (y1 - y2) * (x0 - x2) + (x2 - x1) * (y0 - y2);
    float dr = (y1 - y0) * (x2 - x0) + (x0 - x1) * (y2 - y0);
    bool okf = fabsf(df) > REPS;
    bool okr = fabsf(dr) > REPS;
    if (!okf && !okr) return;

    float xmin = fminf(x0, fminf(x1, x2)), xmax = fmaxf(x0, fmaxf(x1, x2));
    float ymin = fminf(y0, fminf(y1, y2)), ymax = fmaxf(y0, fmaxf(y1, y2));
    const float Sf = (float)IMG;
    int c_lo = max(0,       (int)floorf((xmin * Sf + Sf - 1.0f) * 0.5f));
    int c_hi = min(IMG - 1, (int)ceilf ((xmax * Sf + Sf - 1.0f) * 0.5f));
    int r_lo = max(0,       (int)floorf((ymin * Sf + Sf - 1.0f) * 0.5f));
    int r_hi = min(IMG - 1, (int)ceilf ((ymax * Sf + Sf - 1.0f) * 0.5f));
    if (c_lo > c_hi || r_lo > r_hi) return;

    float zmf = fminf(z0, fminf(z1, z2));

    float nanv = __int_as_float(0x7fffffff);
    float invdf = okf ? (1.0f / df) : nanv;
    float invdr = okr ? (1.0f / dr) : nanv;
    float iz0 = 1.0f / z0, iz1 = 1.0f / z1, iz2 = 1.0f / z2;

    float4 r1; r1.x = y1 - y2; r1.y = x2 - x1; r1.z = y2 - y0; r1.w = x0 - x2;

    if (lane == 0) {
        g_zminf[idx] = zmf;
        float4 r0; r0.x = x2;      r0.y = y2;      r0.z = x0;      r0.w = y0;
        float4 r2f; r2f.x = y1 - y0; r2f.y = x0 - x1; r2f.z = y0 - y2; r2f.w = x2 - x0;
        float4 r3; r3.x = invdf;   r3.y = invdr;   r3.z = zmf;       r3.w = iz0 - iz2;
        float4 r4; r4.x = iz1 - iz2; r4.y = iz2;   r4.z = iz1 - iz0; r4.w = iz0;
        g_rec[idx*5+0] = r0; g_rec[idx*5+1] = r1; g_rec[idx*5+2] = r2f;
        g_rec[idx*5+3] = r3; g_rec[idx*5+4] = r4;
    }

    int packed = (zbucket(zmf) << 24) | idx;   // idx < 40000 fits low bits

    // tile loop distributed across the 4 lanes of this face's group
    float a0 = r1.x * invdf, b0 = r1.y * invdf;
    float a1 = r1.z * invdf, b1 = r1.w * invdf;
    float a2 = -a0 - a1,     b2 = -b0 - b1;
    int tbase = b * TPI * TPI;
    int ty0 = r_lo >> 4, ty1 = r_hi >> 4;
    int tx0 = c_lo >> 4, tx1 = c_hi >> 4;
    int ntx = tx1 - tx0 + 1;
    int ntot = ntx * (ty1 - ty0 + 1);

    for (int i = lane; i < ntot; i += GPF) {
        int ty = ty0 + i / ntx;
        int tx = tx0 + i - (i / ntx) * ntx;
        float ylo = (2.0f * (float)(ty * TSZ)           + 1.0f - Sf) / Sf - y2;
        float yhi = (2.0f * (float)(ty * TSZ + TSZ - 1) + 1.0f - Sf) / Sf - y2;
        float xlo = (2.0f * (float)(tx * TSZ)           + 1.0f - Sf) / Sf - x2;
        float xhi = (2.0f * (float)(tx * TSZ + TSZ - 1) + 1.0f - Sf) / Sf - x2;

        float m0 = a0 * (a0 >= 0.f ? xhi : xlo) + b0 * (b0 >= 0.f ? yhi : ylo);
        float m1 = a1 * (a1 >= 0.f ? xhi : xlo) + b1 * (b1 >= 0.f ? yhi : ylo);
        float m2 = 1.0f + a2 * (a2 >= 0.f ? xhi : xlo) + b2 * (b2 >= 0.f ? yhi : ylo);
        if (m0 < -CULL_M || m1 < -CULL_M || m2 < -CULL_M) continue;

        int t = tbase + ty * TPI + tx;
        int pos = atomicAdd(&g_fill[t], 1);
        if (pos < CAP) g_listA[t * CAP + pos] = packed;
    }
}

// ---------------- per-tile counting sort by packed key (512 thr, no gather) ----------------
__global__ void sort_kernel() {
    int tile = blockIdx.x;
    int len  = min(g_fill[tile], CAP);
    if (len == 0) return;
    int base = tile * CAP;
    int tid = threadIdx.x;
    const unsigned FULL = 0xffffffffu;

    __shared__ int cnt[256];
    __shared__ int off[256];
    __shared__ int wsum[8];
    if (tid < 256) cnt[tid] = 0;
    __syncthreads();

    for (int i = tid; i < len; i += 512) {
        int e = g_listA[base + i];
        atomicAdd(&cnt[(unsigned)e >> 24], 1);
    }
    __syncthreads();

    if (tid < 256) {
        int lane = tid & 31, wrp = tid >> 5;
        int v = cnt[tid];
        int x = v;
        #pragma unroll
        for (int o = 1; o < 32; o <<= 1) {
            int y = __shfl_up_sync(FULL, x, o);
            if (lane >= o) x += y;
        }
        if (lane == 31) wsum[wrp] = x;
        __syncthreads();
        if (tid < 8) {
            int s = wsum[tid];
            int xx = s;
            #pragma unroll
            for (int o = 1; o < 8; o <<= 1) {
                int y = __shfl_up_sync(0xffu, xx, o);
                if (tid >= o) xx += y;
            }
            wsum[tid] = xx - s;
        }
        __syncthreads();
        off[tid] = x + wsum[wrp] - v;
    } else {
        __syncthreads();
        __syncthreads();
    }
    __syncthreads();

    for (int i = tid; i < len; i += 512) {
        int e = g_listA[base + i];
        int q = (unsigned)e >> 24;
        int pos = atomicAdd(&off[q], 1);
        g_listB[base + pos] = e & 0xFFFFFF;
    }
}

// ---------------- init output ----------------
__global__ void init_kernel(float4* __restrict__ out, int n4) {
    int i = blockIdx.x * blockDim.x + threadIdx.x;
    if (i < n4) { float4 v; v.x = v.y = v.z = v.w = FAR_F; out[i] = v; }
}

// ---------------- raster: adaptive slices + reg-double-buffered staging ----------------
__global__ void __launch_bounds__(256) raster_tiles(float* __restrict__ out) {
    int tile  = blockIdx.x / SPLITR;
    int slice = blockIdx.x % SPLITR;
    int len = min(g_fill[tile], CAP);
    // adaptive number of slices: one per ~512 faces, capped at SPLITR
    int nsl = min(SPLITR, 1 + (len >> 9));
    if (slice >= nsl) return;
    int jstart = slice * CH;
    if (len <= jstart) return;

    int b  = tile >> 8;
    int tt = tile & 255;
    int ty = tt >> 4, tx = tt & 15;
    int tid = threadIdx.x;
    int r = ty * TSZ + (tid >> 4);
    int c = tx * TSZ + (tid & 15);
    const float Sf = (float)IMG;
    float xp = (2.0f * (float)c + 1.0f - Sf) / Sf;
    float yp = (2.0f * (float)r + 1.0f - Sf) / Sf;

    int basei = tile * CAP;
    const unsigned FULL = 0xffffffffu;
    int stride = CH * nsl;

    __shared__ float4 srec[CH * 5];
    float zmin = FAR_F;

    // prologue: prefetch first chunk into registers (<=1 float4/thread)
    float4 pre;
    {
        int n0 = min(CH, len - jstart);
        if (tid < n0 * 5) {
            int m = tid / 5, q = tid - m * 5;
            int fidx = g_listB[basei + jstart + m];
            pre = g_rec[fidx * 5 + q];
        }
    }

    for (int j = jstart; j < len; j += stride) {
        int n = min(CH, len - j);
        __syncthreads();
        if (tid < n * 5) srec[tid] = pre;
        __syncthreads();

        // prefetch next chunk: gmem latency overlaps the compute below
        int jn = j + stride;
        if (jn < len) {
            int nn = min(CH, len - jn);
            if (tid < nn * 5) {
                int m = tid / 5, q = tid - m * 5;
                int fidx = g_listB[basei + jn + m];
                pre = g_rec[fidx * 5 + q];
            }
        }

        float bound = zbound(zbucket(srec[3].z));
        if (__syncthreads_and(zmin <= bound)) break;

        for (int m = 0; m < n; m++) {
            float4 q3 = srec[m*5+3];
            if (!__ballot_sync(FULL, q3.z < zmin)) continue;

            float4 q0 = srec[m*5+0];
            float4 q1 = srec[m*5+1];

            float dxf = xp - q0.x, dyf = yp - q0.y;
            float w0 = (q1.x * dxf + q1.y * dyf) * q3.x;
            float w1 = (q1.z * dxf + q1.w * dyf) * q3.x;
            float w2 = 1.0f - w0 - w1;
            bool inf_ = (w0 >= 0.0f) && (w1 >= 0.0f) && (w2 >= 0.0f);
            bool safe = (fabsf(w0) > WMARG) && (fabsf(w1) > WMARG) && (fabsf(w2) > WMARG);

            bool in_ = inf_;
            bool userev = false;
            float w0r = 0.f, w1r = 0.f;
            if (__ballot_sync(FULL, !safe)) {
                float4 q2 = srec[m*5+2];
                float dxr = xp - q0.z, dyr = yp - q0.w;
                w0r = (q2.x * dxr + q2.y * dyr) * q3.y;
                w1r = (q2.z * dxr + q2.w * dyr) * q3.y;
                float w2r = 1.0f - w0r - w1r;
                bool inr_ = (w0r >= 0.0f) && (w1r >= 0.0f) && (w2r >= 0.0f);
                in_ = inf_ || inr_;
                userev = (!inf_) && inr_;
            }

            if (in_) {
                float4 q4 = srec[m*5+4];
                float zinv = userev ? fmaf(w1r, q4.z, fmaf(w0r, -q3.w, q4.w))
                                    : fmaf(w1,  q4.x, fmaf(w0,   q3.w, q4.y));
                float zp = (zinv > REPS) ? __fdividef(1.0f, zinv) : 1.0f;
                if (zp > NEAR_F && zp < FAR_F) zmin = fminf(zmin, zp);
            }
        }
    }

    if (zmin < FAR_F) {
        int* addr = (int*)&out[((size_t)b * IMG + (IMG - 1 - r)) * IMG + c];
        atomicMin(addr, __float_as_int(zmin));
    }
}

extern "C" void kernel_launch(void* const* d_in, const int* in_sizes, int n_in,
                              void* d_out, int out_size) {
    const float* verts = (const float*)d_in[0];
    const int*   faces = (const int*)d_in[1];
    const float* K     = (const float*)d_in[2];
    const float* R     = (const float*)d_in[3];
    const float* t     = (const float*)d_in[4];
    const float* dist  = (const float*)d_in[5];
    float* out = (float*)d_out;

    int B = in_sizes[2] / 9;
    int V = in_sizes[0] / (3 * B);
    int F = in_sizes[1] / (3 * B);
    int ntile = B * TPI * TPI;

    void* fill_ptr = nullptr;
    cudaGetSymbolAddress(&fill_ptr, g_fill);

    int nv = B * V;
    project_kernel<<<(nv + 255) / 256, 256>>>(verts, K, R, t, dist, B, V);

    cudaMemsetAsync(fill_ptr, 0, ntile * sizeof(int));

    int nf = B * F;
    int nthr = nf * GPF;
    prepfill_kernel<<<(nthr + 255) / 256, 256>>>(faces, B, V, F);

    sort_kernel<<<ntile, 512>>>();

    int npix4 = (B * IMG * IMG) / 4;
    init_kernel<<<(npix4 + 255) / 256, 256>>>((float4*)out, npix4);

    raster_tiles<<<ntile * SPLITR, 256>>>(out);
}